// round 12
// baseline (speedup 1.0000x reference)
#include <cuda_runtime.h>

#define NB 32
#define NS 1024
#define NTOK (NB*NS)
#define NV 8

typedef unsigned long long ull;

// smem weight-table offsets (floats); all float4-aligned
#define O_EMB   0     // 32
#define O_LN1G  32    // 8
#define O_LN1B  40    // 8
#define O_WQKV  48    // 96
#define O_WO    144   // 32
#define O_LN2G  176   // 8
#define O_LN2B  184   // 8
#define O_W1    192   // 128
#define O_B1    320   // 32
#define O_W2    352   // 128
#define O_B2    480   // 8
#define O_OUTW  488   // 32
#define O_W2T   520   // 128 (transposed w2: [l][fl][e])
#define W_TOTAL 648

__device__ __forceinline__ float ex2(float x) {
    float y;
    asm("ex2.approx.ftz.f32 %0, %1;" : "=f"(y) : "f"(x));
    return y;
}
__device__ __forceinline__ float4 ld4(const float* p) {
    return *(const float4*)p;
}

// ---------------------------------------------------------------------------
// ONE kernel, one block per batch (256 threads = 8 warps).
//   phase 0: token int4 load + one-shot float4 weight staging (130 float4)
//            + transposed-w2 staging + byte-packed warp histograms. ONE bar.
//   phase 1: replicated histogram extraction (16-bit field sums, no barrier).
//   phase 2: warp w runs the 2-layer network for distinct token-state w
//            (vocab=8, no positional encoding => equal ids share state;
//            attention = histogram-weighted 8-term sum). All weight reads are
//            LDS.128. K/V exchanged via smem (1 bar per layer). FFN is
//            lane-parallel: one gelu/erff per lane, butterfly-reduced.
//   phase 3: scatter the 8x8 logit table: 4 contiguous tokens/thread (STG.128).
// ---------------------------------------------------------------------------
__global__ void __launch_bounds__(256) fused_kernel(
    const int*   __restrict__ tok,
    const float* __restrict__ emb,
    const float* __restrict__ ln1_g, const float* __restrict__ ln1_b,
    const float* __restrict__ wqkv,  const float* __restrict__ wo,
    const float* __restrict__ ln2_g, const float* __restrict__ ln2_b,
    const float* __restrict__ w1,    const float* __restrict__ b1,
    const float* __restrict__ w2,    const float* __restrict__ b2,
    const float* __restrict__ out_w,
    float* __restrict__ out)
{
    __shared__ __align__(16) float sw[W_TOTAL];    // staged weights
    __shared__ ull   whist[8];                     // per-warp packed histograms
    __shared__ __align__(16) float skv[2][8][8];   // [layer][state][k0..3 v0..3]
    __shared__ __align__(16) float slog[8 * NV];   // 8 ids x 8 logits

    const int b    = blockIdx.x;
    const int t    = threadIdx.x;
    const int warp = t >> 5;       // == state id this warp owns
    const int lane = t & 31;

    // ---- phase 0: tokens + histogram + one-shot weight staging ----
    int4 tk = ((const int4*)(tok + b * NS))[t];    // tokens 4t .. 4t+3

    ull c = (1ull << (8 * tk.x)) + (1ull << (8 * tk.y))
          + (1ull << (8 * tk.z)) + (1ull << (8 * tk.w));
    #pragma unroll
    for (int o = 16; o; o >>= 1) c += __shfl_xor_sync(0xffffffffu, c, o);
    if (lane == 0) whist[warp] = c;                // bins <=128/warp: no carry

    if (t < 130) {                                 // one float4 per thread
        const float4* src;
        if      (t < 8)   src = (const float4*)emb   + t;
        else if (t < 10)  src = (const float4*)ln1_g + (t - 8);
        else if (t < 12)  src = (const float4*)ln1_b + (t - 10);
        else if (t < 36)  src = (const float4*)wqkv  + (t - 12);
        else if (t < 44)  src = (const float4*)wo    + (t - 36);
        else if (t < 46)  src = (const float4*)ln2_g + (t - 44);
        else if (t < 48)  src = (const float4*)ln2_b + (t - 46);
        else if (t < 80)  src = (const float4*)w1    + (t - 48);
        else if (t < 88)  src = (const float4*)b1    + (t - 80);
        else if (t < 120) src = (const float4*)w2    + (t - 88);
        else if (t < 122) src = (const float4*)b2    + (t - 120);
        else              src = (const float4*)out_w + (t - 122);
        ((float4*)sw)[t] = *src;
    }
    if (t >= 128) {                                // transposed w2 (128 elems)
        int i  = t - 128;                          // i = l*64 + fl*4 + e
        int l  = i >> 6, fl = (i >> 2) & 15, e = i & 3;
        sw[O_W2T + i] = w2[l * 64 + e * 16 + fl];
    }
    __syncthreads();                               // bar1

    // ---- phase 1: replicated histogram extraction (no barrier) ----
    ull lo = 0, hi = 0;
    #pragma unroll
    for (int w = 0; w < 8; w++) {
        ull v = whist[w];
        lo +=  v       & 0x00FF00FF00FF00FFull;
        hi += (v >> 8) & 0x00FF00FF00FF00FFull;    // sums <= 1024: 16-bit safe
    }
    float cw[8];
    cw[0] = (float)( lo        & 0xFFFF); cw[1] = (float)( hi        & 0xFFFF);
    cw[2] = (float)((lo >> 16) & 0xFFFF); cw[3] = (float)((hi >> 16) & 0xFFFF);
    cw[4] = (float)((lo >> 32) & 0xFFFF); cw[5] = (float)((hi >> 32) & 0xFFFF);
    cw[6] = (float)((lo >> 48) & 0xFFFF); cw[7] = (float)( hi >> 48);

    // ---- phase 2: warp w computes state w ----
    float4 ev = ld4(sw + O_EMB + warp * 4);
    float x0 = ev.x, x1 = ev.y, x2 = ev.z, x3 = ev.w;
    const float SC = 0.70710678118654752f * 1.4426950408889634f;
    const int  fl  = lane & 15;                    // FFN hidden unit this lane owns

    #pragma unroll
    for (int l = 0; l < 2; l++) {
        // LN1 (vector param loads)
        float4 g1 = ld4(sw + O_LN1G + l*4), b1v = ld4(sw + O_LN1B + l*4);
        float mu = 0.25f*(x0+x1+x2+x3);
        float d0 = x0-mu, d1 = x1-mu, d2 = x2-mu, d3 = x3-mu;
        float r  = rsqrtf(0.25f*(d0*d0+d1*d1+d2*d2+d3*d3) + 1e-5f);
        float h0 = d0*r*g1.x+b1v.x, h1 = d1*r*g1.y+b1v.y;
        float h2 = d2*r*g1.z+b1v.z, h3 = d3*r*g1.w+b1v.w;

        // QKV: 12 float4 rows (LDS.128 each)
        float qk[12];
        #pragma unroll
        for (int f = 0; f < 12; f++) {
            float4 wr = ld4(sw + O_WQKV + l*48 + f*4);
            qk[f] = fmaf(h0, wr.x, fmaf(h1, wr.y, fmaf(h2, wr.z, h3 * wr.w)));
        }

        // publish this state's K and V
        if (lane == 0) {
            float4* dst = (float4*)skv[l][warp];
            dst[0] = make_float4(qk[4], qk[5], qk[6],  qk[7]);
            dst[1] = make_float4(qk[8], qk[9], qk[10], qk[11]);
        }
        __syncthreads();                           // bar2 / bar3

        float q00 = qk[0]*SC, q01 = qk[1]*SC;      // head0
        float q10 = qk[2]*SC, q11 = qk[3]*SC;      // head1

        // histogram-weighted softmax over the 8 states (broadcast LDS.128)
        float den0 = 0.f, a00 = 0.f, a01 = 0.f;
        float den1 = 0.f, a10 = 0.f, a11 = 0.f;
        #pragma unroll
        for (int s = 0; s < 8; s++) {
            const float4* kv = (const float4*)skv[l][s];
            float4 k4 = kv[0];
            float4 v4 = kv[1];
            float wa = cw[s] * ex2(fmaf(q00, k4.x, q01*k4.y));
            float wb = cw[s] * ex2(fmaf(q10, k4.z, q11*k4.w));
            den0 += wa; a00 = fmaf(wa, v4.x, a00); a01 = fmaf(wa, v4.y, a01);
            den1 += wb; a10 = fmaf(wb, v4.z, a10); a11 = fmaf(wb, v4.w, a11);
        }
        float inv0 = 1.0f/den0, inv1 = 1.0f/den1;
        float o0 = a00*inv0, o1 = a01*inv0;
        float o2 = a10*inv1, o3 = a11*inv1;

        // Wo projection + residual (4 vector rows)
        float4 wo0 = ld4(sw + O_WO + l*16 + 0);
        float4 wo1 = ld4(sw + O_WO + l*16 + 4);
        float4 wo2 = ld4(sw + O_WO + l*16 + 8);
        float4 wo3 = ld4(sw + O_WO + l*16 + 12);
        float y0 = x0 + o0*wo0.x + o1*wo0.y + o2*wo0.z + o3*wo0.w;
        float y1 = x1 + o0*wo1.x + o1*wo1.y + o2*wo1.z + o3*wo1.w;
        float y2 = x2 + o0*wo2.x + o1*wo2.y + o2*wo2.z + o3*wo2.w;
        float y3 = x3 + o0*wo3.x + o1*wo3.y + o2*wo3.z + o3*wo3.w;

        // LN2
        float4 g2 = ld4(sw + O_LN2G + l*4), b2v = ld4(sw + O_LN2B + l*4);
        mu = 0.25f*(y0+y1+y2+y3);
        d0 = y0-mu; d1 = y1-mu; d2 = y2-mu; d3 = y3-mu;
        r  = rsqrtf(0.25f*(d0*d0+d1*d1+d2*d2+d3*d3) + 1e-5f);
        h0 = d0*r*g2.x+b2v.x; h1 = d1*r*g2.y+b2v.y;
        h2 = d2*r*g2.z+b2v.z; h3 = d3*r*g2.w+b2v.w;

        // FFN: lane fl owns one hidden unit (lanes 16-31 mirror); one erff.
        float4 w1r = ld4(sw + O_W1 + l*64 + fl*4);
        float  bb  = sw[O_B1 + l*16 + fl];
        float s = fmaf(h0, w1r.x, fmaf(h1, w1r.y, fmaf(h2, w1r.z, fmaf(h3, w1r.w, bb))));
        float u = 0.5f * s * (1.0f + erff(s * 0.70710678118654752f)); // exact gelu
        float4 w2r = ld4(sw + O_W2T + l*64 + fl*4);  // transposed: unit fl's 4 outputs
        float p0 = u * w2r.x, p1 = u * w2r.y, p2 = u * w2r.z, p3 = u * w2r.w;
        #pragma unroll
        for (int m = 8; m; m >>= 1) {              // reduce within 16-lane group
            p0 += __shfl_xor_sync(0xffffffffu, p0, m);
            p1 += __shfl_xor_sync(0xffffffffu, p1, m);
            p2 += __shfl_xor_sync(0xffffffffu, p2, m);
            p3 += __shfl_xor_sync(0xffffffffu, p3, m);
        }
        float4 bf2 = ld4(sw + O_B2 + l*4);
        x0 = y0 + bf2.x + p0;
        x1 = y1 + bf2.y + p1;
        x2 = y2 + bf2.z + p2;
        x3 = y3 + bf2.w + p3;
    }

    // final logits: lane v computes logit v of state `warp`
    if (lane < 8) {
        float4 ow = ld4(sw + O_OUTW + lane*4);
        slog[warp * NV + lane] =
            fmaf(x0, ow.x, fmaf(x1, ow.y, fmaf(x2, ow.z, x3 * ow.w)));
    }
    __syncthreads();                               // bar4

    // ---- phase 3: scatter (4 tokens per thread, contiguous 128B) ----
    float4* op = (float4*)(out + ((size_t)b * NS + 4 * t) * NV);
    const float4* l0 = (const float4*)(slog + tk.x * NV);
    const float4* l1 = (const float4*)(slog + tk.y * NV);
    const float4* l2 = (const float4*)(slog + tk.z * NV);
    const float4* l3 = (const float4*)(slog + tk.w * NV);
    op[0] = l0[0]; op[1] = l0[1];
    op[2] = l1[0]; op[3] = l1[1];
    op[4] = l2[0]; op[5] = l2[1];
    op[6] = l3[0]; op[7] = l3[1];
}

// ---------------------------------------------------------------------------
extern "C" void kernel_launch(void* const* d_in, const int* in_sizes, int n_in,
                              void* d_out, int out_size)
{
    const int*   tok   = (const int*)  d_in[0];
    const float* emb   = (const float*)d_in[1];
    const float* ln1_g = (const float*)d_in[2];
    const float* ln1_b = (const float*)d_in[3];
    const float* wqkv  = (const float*)d_in[4];
    const float* wo    = (const float*)d_in[5];
    const float* ln2_g = (const float*)d_in[6];
    const float* ln2_b = (const float*)d_in[7];
    const float* w1    = (const float*)d_in[8];
    const float* b1    = (const float*)d_in[9];
    const float* w2    = (const float*)d_in[10];
    const float* b2    = (const float*)d_in[11];
    const float* out_w = (const float*)d_in[12];
    float* out = (float*)d_out;

    fused_kernel<<<NB, 256>>>(tok, emb, ln1_g, ln1_b, wqkv, wo,
                              ln2_g, ln2_b, w1, b1, w2, b2, out_w, out);
}